// round 2
// baseline (speedup 1.0000x reference)
#include <cuda_runtime.h>
#include <math.h>

#define NN   50000
#define NE   500000
#define IND  64
#define ED   16
#define HID  256
#define NH   4
#define NL   4
#define NG   64
#define BN_EPS 1e-5f

// ---------------- scratch (static __device__ arrays; no allocation) ----------------
__device__ __align__(16) float    g_x[(size_t)NN * HID];       // current node features
__device__ __align__(16) float    g_nf[(size_t)NN * 1024];     // q|k|v|skip per node (stride 1024)
__device__ __align__(16) float    g_attn[(size_t)NN * HID];    // attention numerator accum -> x_pre
__device__ __align__(16) float    g_logit[(size_t)NE * NH];    // per-edge per-head logits
__device__            unsigned    g_maxv[NN * NH];             // order-encoded float max
__device__            float       g_denom[NN * NH];
__device__            float       g_stats[2 * HID];            // col sum, col sumsq
__device__            float       g_pool[NG * HID];            // per-graph sums
__device__            float       g_cnt[NG];

// ---------------- helpers ----------------
__device__ __forceinline__ unsigned enc_f(float f) {
    unsigned u = __float_as_uint(f);
    return (u & 0x80000000u) ? ~u : (u | 0x80000000u);
}
__device__ __forceinline__ float dec_f(unsigned u) {
    return (u & 0x80000000u) ? __uint_as_float(u ^ 0x80000000u) : __uint_as_float(~u);
}

// ---------------- per-layer scratch clear (pure kernel; no cudaMemset) ----------------
// zeroes g_maxv, g_denom, g_attn, g_stats in one grid-stride launch
#define CLR_TOTAL (NN * NH + NN * NH + NN * HID + 2 * HID)
__global__ void __launch_bounds__(256) clear_layer_kernel()
{
    size_t i = (size_t)blockIdx.x * blockDim.x + threadIdx.x;
    size_t stride = (size_t)gridDim.x * blockDim.x;
    for (; i < (size_t)CLR_TOTAL; i += stride) {
        size_t j = i;
        if (j < (size_t)NN * NH) { g_maxv[j] = 0u; continue; }
        j -= (size_t)NN * NH;
        if (j < (size_t)NN * NH) { g_denom[j] = 0.f; continue; }
        j -= (size_t)NN * NH;
        if (j < (size_t)NN * HID) { g_attn[j] = 0.f; continue; }
        j -= (size_t)NN * HID;
        g_stats[j] = 0.f;
    }
}

__global__ void __launch_bounds__(256) clear_pool_kernel()
{
    int i = blockIdx.x * blockDim.x + threadIdx.x;
    if (i < NG * HID) g_pool[i] = 0.f;
    if (i < NG) g_cnt[i] = 0.f;
}

// ---------------- tiled fp32 GEMM: C[M, 128cols] = A[M,K] @ B[K,*] + bias ----------------
// block: 256 threads, tile 128x128, BK=8, 8x8 microtile per thread
__global__ void __launch_bounds__(256) sgemm128(
    const float* __restrict__ A, const float* __restrict__ B,
    const float* __restrict__ bias, float* __restrict__ C,
    int M, int K, int ldb, int ldc)
{
    __shared__ __align__(16) float As[8][128];
    __shared__ __align__(16) float Bs[8][128];

    const int tid = threadIdx.x;
    const int tx = tid & 15;        // 0..15 (col group)
    const int ty = tid >> 4;        // 0..15 (row group)
    const int row0 = blockIdx.x * 128;
    const int col0 = blockIdx.y * 128;

    const int arow = tid >> 1;          // 0..127
    const int akk  = (tid & 1) * 4;     // 0 or 4
    const int brow = tid >> 5;          // 0..7
    const int bcol = (tid & 31) * 4;    // 0..124

    float acc[8][8];
#pragma unroll
    for (int i = 0; i < 8; i++)
#pragma unroll
        for (int j = 0; j < 8; j++) acc[i][j] = 0.f;

    for (int kt = 0; kt < K; kt += 8) {
        float4 av = make_float4(0.f, 0.f, 0.f, 0.f);
        int r = row0 + arow;
        if (r < M) av = *(const float4*)(A + (size_t)r * K + kt + akk);
        As[akk + 0][arow] = av.x; As[akk + 1][arow] = av.y;
        As[akk + 2][arow] = av.z; As[akk + 3][arow] = av.w;

        float4 bv = *(const float4*)(B + (size_t)(kt + brow) * ldb + col0 + bcol);
        *(float4*)(&Bs[brow][bcol]) = bv;

        __syncthreads();
#pragma unroll
        for (int k = 0; k < 8; k++) {
            float ra[8], rb[8];
            *(float4*)(ra)     = *(const float4*)(&As[k][ty * 8]);
            *(float4*)(ra + 4) = *(const float4*)(&As[k][ty * 8 + 4]);
            *(float4*)(rb)     = *(const float4*)(&Bs[k][tx * 8]);
            *(float4*)(rb + 4) = *(const float4*)(&Bs[k][tx * 8 + 4]);
#pragma unroll
            for (int i = 0; i < 8; i++)
#pragma unroll
                for (int j = 0; j < 8; j++) acc[i][j] += ra[i] * rb[j];
        }
        __syncthreads();
    }

    float bvals[8];
#pragma unroll
    for (int j = 0; j < 8; j++) bvals[j] = bias[col0 + tx * 8 + j];

#pragma unroll
    for (int i = 0; i < 8; i++) {
        int r = row0 + ty * 8 + i;
        if (r < M) {
            float v[8];
#pragma unroll
            for (int j = 0; j < 8; j++) v[j] = acc[i][j] + bvals[j];
            float* cp = C + (size_t)r * ldc + col0 + tx * 8;
            *(float4*)(cp)     = *(float4*)(v);
            *(float4*)(cp + 4) = *(float4*)(v + 4);
        }
    }
}

// ---------------- edge pass A: logits + segment max ----------------
// one warp per edge; lane handles 8 contiguous channels; head = lane/8
__global__ void __launch_bounds__(256) edge_logits_kernel(
    const int* __restrict__ ei, const float* __restrict__ eattr,
    const float* __restrict__ We, const float* __restrict__ be)
{
    int e = blockIdx.x * 8 + (threadIdx.x >> 5);
    if (e >= NE) return;
    int lane = threadIdx.x & 31;
    int src = ei[e];
    int dst = ei[NE + e];
    int c0 = lane * 8;

    float ea[16];
    {
        const float4* eap = (const float4*)(eattr + (size_t)e * ED);
        float4 t0 = eap[0], t1 = eap[1], t2 = eap[2], t3 = eap[3];
        ea[0]=t0.x; ea[1]=t0.y; ea[2]=t0.z; ea[3]=t0.w;
        ea[4]=t1.x; ea[5]=t1.y; ea[6]=t1.z; ea[7]=t1.w;
        ea[8]=t2.x; ea[9]=t2.y; ea[10]=t2.z; ea[11]=t2.w;
        ea[12]=t3.x; ea[13]=t3.y; ea[14]=t3.z; ea[15]=t3.w;
    }
    float ev[8];
    {
        const float4* bp = (const float4*)(be + c0);
        float4 b0 = bp[0], b1 = bp[1];
        ev[0]=b0.x; ev[1]=b0.y; ev[2]=b0.z; ev[3]=b0.w;
        ev[4]=b1.x; ev[5]=b1.y; ev[6]=b1.z; ev[7]=b1.w;
    }
#pragma unroll
    for (int f = 0; f < ED; f++) {
        const float4* wp = (const float4*)(We + (size_t)f * HID + c0);
        float4 w0 = wp[0], w1 = wp[1];
        float a = ea[f];
        ev[0] += a * w0.x; ev[1] += a * w0.y; ev[2] += a * w0.z; ev[3] += a * w0.w;
        ev[4] += a * w1.x; ev[5] += a * w1.y; ev[6] += a * w1.z; ev[7] += a * w1.w;
    }

    const float4* qp = (const float4*)(g_nf + (size_t)dst * 1024 + c0);
    const float4* kp = (const float4*)(g_nf + (size_t)src * 1024 + HID + c0);
    float4 q0 = qp[0], q1 = qp[1];
    float4 k0 = kp[0], k1 = kp[1];

    float s = q0.x * (k0.x + ev[0]) + q0.y * (k0.y + ev[1])
            + q0.z * (k0.z + ev[2]) + q0.w * (k0.w + ev[3])
            + q1.x * (k1.x + ev[4]) + q1.y * (k1.y + ev[5])
            + q1.z * (k1.z + ev[6]) + q1.w * (k1.w + ev[7]);

    s += __shfl_xor_sync(0xffffffffu, s, 4);
    s += __shfl_xor_sync(0xffffffffu, s, 2);
    s += __shfl_xor_sync(0xffffffffu, s, 1);

    if ((lane & 7) == 0) {
        int h = lane >> 3;
        float a = s * 0.125f;  // 1/sqrt(64)
        g_logit[(size_t)e * NH + h] = a;
        atomicMax(&g_maxv[dst * NH + h], enc_f(a));
    }
}

// ---------------- edge pass B: exp + weighted scatter ----------------
__global__ void __launch_bounds__(256) edge_accum_kernel(
    const int* __restrict__ ei, const float* __restrict__ eattr,
    const float* __restrict__ We, const float* __restrict__ be)
{
    int e = blockIdx.x * 8 + (threadIdx.x >> 5);
    if (e >= NE) return;
    int lane = threadIdx.x & 31;
    int src = ei[e];
    int dst = ei[NE + e];
    int c0 = lane * 8;
    int h = lane >> 3;

    float m = dec_f(g_maxv[dst * NH + h]);
    float w = __expf(g_logit[(size_t)e * NH + h] - m);

    float ea[16];
    {
        const float4* eap = (const float4*)(eattr + (size_t)e * ED);
        float4 t0 = eap[0], t1 = eap[1], t2 = eap[2], t3 = eap[3];
        ea[0]=t0.x; ea[1]=t0.y; ea[2]=t0.z; ea[3]=t0.w;
        ea[4]=t1.x; ea[5]=t1.y; ea[6]=t1.z; ea[7]=t1.w;
        ea[8]=t2.x; ea[9]=t2.y; ea[10]=t2.z; ea[11]=t2.w;
        ea[12]=t3.x; ea[13]=t3.y; ea[14]=t3.z; ea[15]=t3.w;
    }
    float ev[8];
    {
        const float4* bp = (const float4*)(be + c0);
        float4 b0 = bp[0], b1 = bp[1];
        ev[0]=b0.x; ev[1]=b0.y; ev[2]=b0.z; ev[3]=b0.w;
        ev[4]=b1.x; ev[5]=b1.y; ev[6]=b1.z; ev[7]=b1.w;
    }
#pragma unroll
    for (int f = 0; f < ED; f++) {
        const float4* wp = (const float4*)(We + (size_t)f * HID + c0);
        float4 w0 = wp[0], w1 = wp[1];
        float a = ea[f];
        ev[0] += a * w0.x; ev[1] += a * w0.y; ev[2] += a * w0.z; ev[3] += a * w0.w;
        ev[4] += a * w1.x; ev[5] += a * w1.y; ev[6] += a * w1.z; ev[7] += a * w1.w;
    }

    const float4* vp = (const float4*)(g_nf + (size_t)src * 1024 + 2 * HID + c0);
    float4 v0 = vp[0], v1 = vp[1];

    if ((lane & 7) == 0) atomicAdd(&g_denom[dst * NH + h], w);

    float a0 = w * (v0.x + ev[0]), a1 = w * (v0.y + ev[1]);
    float a2 = w * (v0.z + ev[2]), a3 = w * (v0.w + ev[3]);
    float a4 = w * (v1.x + ev[4]), a5 = w * (v1.y + ev[5]);
    float a6 = w * (v1.z + ev[6]), a7 = w * (v1.w + ev[7]);

    float* op = g_attn + (size_t)dst * HID + c0;
    asm volatile("red.global.add.v4.f32 [%0], {%1,%2,%3,%4};"
                 :: "l"(op), "f"(a0), "f"(a1), "f"(a2), "f"(a3) : "memory");
    asm volatile("red.global.add.v4.f32 [%0], {%1,%2,%3,%4};"
                 :: "l"(op + 4), "f"(a4), "f"(a5), "f"(a6), "f"(a7) : "memory");
}

// ---------------- node finalize: normalize + beta gate ----------------
__global__ void __launch_bounds__(256) finalize_kernel(const float* __restrict__ Wb)
{
    __shared__ float red[8];
    int n = blockIdx.x;
    int c = threadIdx.x;

    float d = g_denom[n * NH + (c >> 6)];
    float o = g_attn[(size_t)n * HID + c];
    o = (d > 0.f) ? (o / d) : 0.f;
    float sk = g_nf[(size_t)n * 1024 + 3 * HID + c];

    float p = o * (Wb[c] + Wb[2 * HID + c]) + sk * (Wb[HID + c] - Wb[2 * HID + c]);
#pragma unroll
    for (int off = 16; off; off >>= 1) p += __shfl_xor_sync(0xffffffffu, p, off);
    if ((c & 31) == 0) red[c >> 5] = p;
    __syncthreads();
    if (c == 0) {
        float t = 0.f;
#pragma unroll
        for (int i = 0; i < 8; i++) t += red[i];
        red[0] = t;
    }
    __syncthreads();
    float beta = 1.f / (1.f + __expf(-red[0]));
    g_attn[(size_t)n * HID + c] = beta * sk + (1.f - beta) * o;
}

// ---------------- batchnorm stats (col sums over nodes) ----------------
__global__ void __launch_bounds__(256) bnstats_kernel()
{
    int c = threadIdx.x;
    int r0 = blockIdx.x * 128;
    int r1 = min(r0 + 128, NN);
    float s = 0.f, s2 = 0.f;
    for (int r = r0; r < r1; r++) {
        float v = g_attn[(size_t)r * HID + c];
        s += v; s2 += v * v;
    }
    atomicAdd(&g_stats[c], s);
    atomicAdd(&g_stats[HID + c], s2);
}

// ---------------- batchnorm apply + LeakyReLU ----------------
__global__ void __launch_bounds__(256) bnapply_kernel(
    const float* __restrict__ gamma, const float* __restrict__ bbeta)
{
    size_t idx = (size_t)blockIdx.x * blockDim.x + threadIdx.x;
    if (idx >= (size_t)NN * HID) return;
    int c = (int)(idx & (HID - 1));
    const float invN = 1.f / (float)NN;
    float mu = g_stats[c] * invN;
    float var = g_stats[HID + c] * invN - mu * mu;
    var = fmaxf(var, 0.f);
    float y = (g_attn[idx] - mu) * rsqrtf(var + BN_EPS) * gamma[c] + bbeta[c];
    g_x[idx] = (y >= 0.f) ? y : 0.1f * y;
}

// ---------------- pooling (batch is sorted) ----------------
__global__ void __launch_bounds__(256) pool_kernel(const int* __restrict__ batch)
{
    int c = threadIdx.x;
    int r0 = blockIdx.x * 128;
    if (r0 >= NN) return;
    int r1 = min(r0 + 128, NN);
    int cur = batch[r0];
    float s = 0.f;
    int run = 0;
    for (int r = r0; r < r1; r++) {
        int b = batch[r];
        if (b != cur) {
            atomicAdd(&g_pool[cur * HID + c], s);
            if (c == 0) atomicAdd(&g_cnt[cur], (float)run);
            s = 0.f; run = 0; cur = b;
        }
        s += g_x[(size_t)r * HID + c];
        run++;
    }
    atomicAdd(&g_pool[cur * HID + c], s);
    if (c == 0) atomicAdd(&g_cnt[cur], (float)run);
}

// ---------------- head ----------------
__global__ void __launch_bounds__(256) head_kernel(
    const float* __restrict__ hW, const float* __restrict__ hb,
    float* __restrict__ out)
{
    __shared__ float red[8];
    int g = blockIdx.x;
    int c = threadIdx.x;
    float s = g_pool[g * HID + c];
    float ct = fmaxf(g_cnt[g], 1.f);
    float p = (s / ct) * hW[c] + s * hW[HID + c];
#pragma unroll
    for (int off = 16; off; off >>= 1) p += __shfl_xor_sync(0xffffffffu, p, off);
    if ((c & 31) == 0) red[c >> 5] = p;
    __syncthreads();
    if (c == 0) {
        float t = 0.f;
#pragma unroll
        for (int i = 0; i < 8; i++) t += red[i];
        out[g] = t + hb[0];
    }
}

// device-global pointer accessor kernels are unnecessary: all scratch is
// referenced directly inside kernels; kernel_launch only passes harness
// input pointers.

extern "C" void kernel_launch(void* const* d_in, const int* in_sizes, int n_in,
                              void* d_out, int out_size)
{
    const float* node_features = (const float*)d_in[0];
    const int*   edge_index    = (const int*)d_in[1];
    const float* edge_attr     = (const float*)d_in[2];
    const int*   batch         = (const int*)d_in[3];
    const float* proj_W        = (const float*)d_in[4];
    const float* proj_b        = (const float*)d_in[5];
    const float* Wq            = (const float*)d_in[6];
    const float* bq            = (const float*)d_in[7];
    const float* Wk            = (const float*)d_in[8];
    const float* bk            = (const float*)d_in[9];
    const float* Wv            = (const float*)d_in[10];
    const float* bv            = (const float*)d_in[11];
    const float* We            = (const float*)d_in[12];
    const float* be            = (const float*)d_in[13];
    const float* Wskip         = (const float*)d_in[14];
    const float* bskip         = (const float*)d_in[15];
    const float* Wbeta         = (const float*)d_in[16];
    const float* bng           = (const float*)d_in[17];
    const float* bnb           = (const float*)d_in[18];
    const float* headW         = (const float*)d_in[19];
    const float* headb         = (const float*)d_in[20];
    float* out = (float*)d_out;

    // GEMM output targets: we need device addresses of g_x / g_nf for the C
    // pointer of sgemm128. Obtain once via cudaGetSymbolAddress is avoided;
    // instead sgemm128 writes through a pointer parameter, so we fetch the
    // addresses with cudaGetSymbolAddress OUTSIDE the graph-captured region
    // is not possible here — therefore sgemm128 selects its destination via
    // an integer tag instead.
    // dst_tag: 0 -> g_x, 1..4 -> g_nf + (tag-1)*HID (ldc 1024)

    dim3 gNode((NN + 127) / 128, 2);

    // input projection: x = node_features @ proj_W + proj_b
    // Use a small wrapper: pass nullptr C with tag via template-free approach.
    // Simplest correct approach: pointers to device globals obtained via
    // kernels is overkill; cudaGetSymbolAddress is a pure host-side query
    // (no stream interaction) and is legal during capture.
    float *px, *pnf;
    cudaGetSymbolAddress((void**)&px,  g_x);
    cudaGetSymbolAddress((void**)&pnf, g_nf);

    sgemm128<<<gNode, 256>>>(node_features, proj_W, proj_b, px, NN, IND, HID, HID);

    for (int l = 0; l < NL; l++) {
        clear_layer_kernel<<<2048, 256>>>();

        const float* Ws[4] = { Wq + (size_t)l * HID * HID, Wk + (size_t)l * HID * HID,
                               Wv + (size_t)l * HID * HID, Wskip + (size_t)l * HID * HID };
        const float* bs[4] = { bq + l * HID, bk + l * HID, bv + l * HID, bskip + l * HID };
        for (int w = 0; w < 4; w++)
            sgemm128<<<gNode, 256>>>(px, Ws[w], bs[w], pnf + w * HID, NN, HID, HID, 1024);

        const float* Wel = We + (size_t)l * ED * HID;
        const float* bel = be + l * HID;
        edge_logits_kernel<<<NE / 8, 256>>>(edge_index, edge_attr, Wel, bel);
        edge_accum_kernel<<<NE / 8, 256>>>(edge_index, edge_attr, Wel, bel);
        finalize_kernel<<<NN, 256>>>(Wbeta + (size_t)l * 3 * HID);
        bnstats_kernel<<<(NN + 127) / 128, 256>>>();
        bnapply_kernel<<<(NN * HID + 255) / 256, 256>>>(bng + l * HID, bnb + l * HID);
    }

    clear_pool_kernel<<<(NG * HID + 255) / 256, 256>>>();
    pool_kernel<<<(NN + 127) / 128, 256>>>(batch);
    head_kernel<<<NG, 256>>>(headW, headb, out);
}

// round 3
// speedup vs baseline: 1.2972x; 1.2972x over previous
#include <cuda_runtime.h>
#include <math.h>

#define NN   50000
#define NE   500000
#define IND  64
#define ED   16
#define HID  256
#define NH   4
#define NL   4
#define NG   64
#define BN_EPS 1e-5f

// ---------------- scratch (static __device__ arrays; no allocation) ----------------
__device__ __align__(16) float g_x[(size_t)NN * HID];     // current node features
__device__ __align__(16) float g_nf[(size_t)NN * 1024];   // q|k|v|skip per node (stride 1024)
__device__ __align__(16) float g_attn[(size_t)NN * HID];  // post-attention features
__device__ float g_stats[2 * HID];                        // col sum, col sumsq
__device__ float g_pool[NG * HID];
__device__ float g_cnt[NG];
// CSR by destination
__device__ int  g_deg[NN];
__device__ int  g_rowptr[NN + 1];
__device__ int  g_cursor[NN];
__device__ __align__(8) int2 g_adj[NE];                   // (src, edge_id)

// ================= CSR build (once per call; edges are layer-invariant) =================
__global__ void __launch_bounds__(256) clear_deg_kernel()
{
    int i = blockIdx.x * 256 + threadIdx.x;
    if (i < NN) g_deg[i] = 0;
}

__global__ void __launch_bounds__(256) hist_kernel(const int* __restrict__ ei)
{
    int i = blockIdx.x * 256 + threadIdx.x;
    if (i < NE) atomicAdd(&g_deg[ei[NE + i]], 1);
}

// single-block exclusive scan of g_deg -> g_rowptr (+ g_cursor copy)
#define SCAN_T 1024
#define SCAN_ITEMS ((NN + SCAN_T - 1) / SCAN_T)
__global__ void __launch_bounds__(SCAN_T) scan_kernel()
{
    __shared__ int wsum[32];
    int t = threadIdx.x;
    int lo = t * SCAN_ITEMS;
    int hi = min(lo + SCAN_ITEMS, NN);
    int s = 0;
    for (int i = lo; i < hi; i++) s += g_deg[i];

    int lane = t & 31, w = t >> 5;
    int v = s;
#pragma unroll
    for (int o = 1; o < 32; o <<= 1) {
        int u = __shfl_up_sync(0xffffffffu, v, o);
        if (lane >= o) v += u;
    }
    if (lane == 31) wsum[w] = v;
    __syncthreads();
    if (w == 0) {
        int x = wsum[lane];
#pragma unroll
        for (int o = 1; o < 32; o <<= 1) {
            int u = __shfl_up_sync(0xffffffffu, x, o);
            if (lane >= o) x += u;
        }
        wsum[lane] = x;
    }
    __syncthreads();
    int excl = v - s + (w ? wsum[w - 1] : 0);

    int run = excl;
    for (int i = lo; i < hi; i++) {
        g_rowptr[i] = run;
        g_cursor[i] = run;
        run += g_deg[i];
    }
    if (t == SCAN_T - 1) g_rowptr[NN] = excl + s;   // total edges
}

__global__ void __launch_bounds__(256) scatter_kernel(const int* __restrict__ ei)
{
    int i = blockIdx.x * 256 + threadIdx.x;
    if (i < NE) {
        int dst = ei[NE + i];
        int pos = atomicAdd(&g_cursor[dst], 1);
        g_adj[pos] = make_int2(ei[i], i);
    }
}

// ================= misc clears =================
__global__ void __launch_bounds__(512) clear_stats_kernel()
{
    g_stats[threadIdx.x] = 0.f;
}

__global__ void __launch_bounds__(256) clear_pool_kernel()
{
    int i = blockIdx.x * 256 + threadIdx.x;
    if (i < NG * HID) g_pool[i] = 0.f;
    if (i < NG) g_cnt[i] = 0.f;
}

// ---------------- tiled fp32 GEMM: C[M,128cols] = A[M,K] @ B[K,*] + bias ----------------
__global__ void __launch_bounds__(256) sgemm128(
    const float* __restrict__ A, const float* __restrict__ B,
    const float* __restrict__ bias, float* __restrict__ C,
    int M, int K, int ldb, int ldc)
{
    __shared__ __align__(16) float As[8][128];
    __shared__ __align__(16) float Bs[8][128];

    const int tid = threadIdx.x;
    const int tx = tid & 15;
    const int ty = tid >> 4;
    const int row0 = blockIdx.x * 128;
    const int col0 = blockIdx.y * 128;

    const int arow = tid >> 1;
    const int akk  = (tid & 1) * 4;
    const int brow = tid >> 5;
    const int bcol = (tid & 31) * 4;

    float acc[8][8];
#pragma unroll
    for (int i = 0; i < 8; i++)
#pragma unroll
        for (int j = 0; j < 8; j++) acc[i][j] = 0.f;

    for (int kt = 0; kt < K; kt += 8) {
        float4 av = make_float4(0.f, 0.f, 0.f, 0.f);
        int r = row0 + arow;
        if (r < M) av = *(const float4*)(A + (size_t)r * K + kt + akk);
        As[akk + 0][arow] = av.x; As[akk + 1][arow] = av.y;
        As[akk + 2][arow] = av.z; As[akk + 3][arow] = av.w;

        float4 bv = *(const float4*)(B + (size_t)(kt + brow) * ldb + col0 + bcol);
        *(float4*)(&Bs[brow][bcol]) = bv;

        __syncthreads();
#pragma unroll
        for (int k = 0; k < 8; k++) {
            float ra[8], rb[8];
            *(float4*)(ra)     = *(const float4*)(&As[k][ty * 8]);
            *(float4*)(ra + 4) = *(const float4*)(&As[k][ty * 8 + 4]);
            *(float4*)(rb)     = *(const float4*)(&Bs[k][tx * 8]);
            *(float4*)(rb + 4) = *(const float4*)(&Bs[k][tx * 8 + 4]);
#pragma unroll
            for (int i = 0; i < 8; i++)
#pragma unroll
                for (int j = 0; j < 8; j++) acc[i][j] += ra[i] * rb[j];
        }
        __syncthreads();
    }

    float bvals[8];
#pragma unroll
    for (int j = 0; j < 8; j++) bvals[j] = bias[col0 + tx * 8 + j];

#pragma unroll
    for (int i = 0; i < 8; i++) {
        int r = row0 + ty * 8 + i;
        if (r < M) {
            float v[8];
#pragma unroll
            for (int j = 0; j < 8; j++) v[j] = acc[i][j] + bvals[j];
            float* cp = C + (size_t)r * ldc + col0 + tx * 8;
            *(float4*)(cp)     = *(float4*)(v);
            *(float4*)(cp + 4) = *(float4*)(v + 4);
        }
    }
}

// ================= fused attention: one warp per dst node, online softmax =================
// gathers k/v per incoming edge via CSR, computes edge features from smem-cached We,
// online-softmax accumulates, then applies the beta gate. Writes g_attn[n].
__global__ void __launch_bounds__(256) attn_kernel(
    const float* __restrict__ eattr, const float* __restrict__ We,
    const float* __restrict__ be, const float* __restrict__ Wb)
{
    __shared__ __align__(16) float sWe[ED][HID];   // 16 KB
    __shared__ float sbe[HID];

    for (int i = threadIdx.x; i < ED * HID; i += 256)
        sWe[i >> 8][i & 255] = We[i];
    if (threadIdx.x < HID) sbe[threadIdx.x] = be[threadIdx.x];
    __syncthreads();

    int n = blockIdx.x * 8 + (threadIdx.x >> 5);
    if (n >= NN) return;
    int lane = threadIdx.x & 31;
    int c0 = lane * 8;

    const float4* qp = (const float4*)(g_nf + (size_t)n * 1024 + c0);
    float4 q0 = qp[0], q1 = qp[1];

    float evb[8];
    {
        const float4* bp = (const float4*)(&sbe[c0]);
        float4 b0 = bp[0], b1 = bp[1];
        evb[0]=b0.x; evb[1]=b0.y; evb[2]=b0.z; evb[3]=b0.w;
        evb[4]=b1.x; evb[5]=b1.y; evb[6]=b1.z; evb[7]=b1.w;
    }

    float m = -INFINITY, d = 0.f;
    float acc[8] = {0.f,0.f,0.f,0.f,0.f,0.f,0.f,0.f};

    int beg = g_rowptr[n], end = g_rowptr[n + 1];
    for (int i = beg; i < end; i++) {
        int2 se = g_adj[i];
        int src = se.x, e = se.y;

        float ea[16];
        {
            const float4* eap = (const float4*)(eattr + (size_t)e * ED);
            float4 t0 = eap[0], t1 = eap[1], t2 = eap[2], t3 = eap[3];
            ea[0]=t0.x; ea[1]=t0.y; ea[2]=t0.z; ea[3]=t0.w;
            ea[4]=t1.x; ea[5]=t1.y; ea[6]=t1.z; ea[7]=t1.w;
            ea[8]=t2.x; ea[9]=t2.y; ea[10]=t2.z; ea[11]=t2.w;
            ea[12]=t3.x; ea[13]=t3.y; ea[14]=t3.z; ea[15]=t3.w;
        }
        float ev[8];
#pragma unroll
        for (int j = 0; j < 8; j++) ev[j] = evb[j];
#pragma unroll
        for (int f = 0; f < ED; f++) {
            const float4* wp = (const float4*)(&sWe[f][c0]);
            float4 w0 = wp[0], w1 = wp[1];
            float a = ea[f];
            ev[0] += a * w0.x; ev[1] += a * w0.y; ev[2] += a * w0.z; ev[3] += a * w0.w;
            ev[4] += a * w1.x; ev[5] += a * w1.y; ev[6] += a * w1.z; ev[7] += a * w1.w;
        }

        const float4* kp = (const float4*)(g_nf + (size_t)src * 1024 + HID + c0);
        const float4* vp = (const float4*)(g_nf + (size_t)src * 1024 + 2 * HID + c0);
        float4 k0 = kp[0], k1 = kp[1];
        float4 v0 = vp[0], v1 = vp[1];

        float s = q0.x * (k0.x + ev[0]) + q0.y * (k0.y + ev[1])
                + q0.z * (k0.z + ev[2]) + q0.w * (k0.w + ev[3])
                + q1.x * (k1.x + ev[4]) + q1.y * (k1.y + ev[5])
                + q1.z * (k1.z + ev[6]) + q1.w * (k1.w + ev[7]);
        s += __shfl_xor_sync(0xffffffffu, s, 4);
        s += __shfl_xor_sync(0xffffffffu, s, 2);
        s += __shfl_xor_sync(0xffffffffu, s, 1);
        float alpha = s * 0.125f;   // 1/sqrt(64)

        float mn = fmaxf(m, alpha);
        float scale = __expf(m - mn);     // m=-inf first iter -> 0
        float w = __expf(alpha - mn);
        d = d * scale + w;
        acc[0] = acc[0] * scale + w * (v0.x + ev[0]);
        acc[1] = acc[1] * scale + w * (v0.y + ev[1]);
        acc[2] = acc[2] * scale + w * (v0.z + ev[2]);
        acc[3] = acc[3] * scale + w * (v0.w + ev[3]);
        acc[4] = acc[4] * scale + w * (v1.x + ev[4]);
        acc[5] = acc[5] * scale + w * (v1.y + ev[5]);
        acc[6] = acc[6] * scale + w * (v1.z + ev[6]);
        acc[7] = acc[7] * scale + w * (v1.w + ev[7]);
        m = mn;
    }

    float inv = (d > 0.f) ? (1.f / d) : 0.f;
    float o[8];
#pragma unroll
    for (int j = 0; j < 8; j++) o[j] = acc[j] * inv;

    float sk[8];
    {
        const float4* sp = (const float4*)(g_nf + (size_t)n * 1024 + 3 * HID + c0);
        float4 s0 = sp[0], s1 = sp[1];
        sk[0]=s0.x; sk[1]=s0.y; sk[2]=s0.z; sk[3]=s0.w;
        sk[4]=s1.x; sk[5]=s1.y; sk[6]=s1.z; sk[7]=s1.w;
    }

    // beta = sigmoid([out | x_r | out - x_r] . Wb) = sigmoid(out.(W0+W2) + x_r.(W1-W2))
    float p = 0.f;
#pragma unroll
    for (int j = 0; j < 8; j++) {
        int c = c0 + j;
        p += o[j] * (Wb[c] + Wb[2 * HID + c]) + sk[j] * (Wb[HID + c] - Wb[2 * HID + c]);
    }
#pragma unroll
    for (int off = 16; off; off >>= 1) p += __shfl_xor_sync(0xffffffffu, p, off);
    float beta = 1.f / (1.f + __expf(-p));

    float* op = g_attn + (size_t)n * HID + c0;
    float r[8];
#pragma unroll
    for (int j = 0; j < 8; j++) r[j] = beta * sk[j] + (1.f - beta) * o[j];
    *(float4*)(op)     = *(float4*)(r);
    *(float4*)(op + 4) = *(float4*)(r + 4);
}

// ---------------- batchnorm stats ----------------
__global__ void __launch_bounds__(256) bnstats_kernel()
{
    int c = threadIdx.x;
    int r0 = blockIdx.x * 128;
    int r1 = min(r0 + 128, NN);
    float s = 0.f, s2 = 0.f;
    for (int r = r0; r < r1; r++) {
        float v = g_attn[(size_t)r * HID + c];
        s += v; s2 += v * v;
    }
    atomicAdd(&g_stats[c], s);
    atomicAdd(&g_stats[HID + c], s2);
}

// ---------------- batchnorm apply + LeakyReLU ----------------
__global__ void __launch_bounds__(256) bnapply_kernel(
    const float* __restrict__ gamma, const float* __restrict__ bbeta)
{
    size_t idx = (size_t)blockIdx.x * blockDim.x + threadIdx.x;
    if (idx >= (size_t)NN * HID) return;
    int c = (int)(idx & (HID - 1));
    const float invN = 1.f / (float)NN;
    float mu = g_stats[c] * invN;
    float var = g_stats[HID + c] * invN - mu * mu;
    var = fmaxf(var, 0.f);
    float y = (g_attn[idx] - mu) * rsqrtf(var + BN_EPS) * gamma[c] + bbeta[c];
    g_x[idx] = (y >= 0.f) ? y : 0.1f * y;
}

// ---------------- pooling (batch is sorted) ----------------
__global__ void __launch_bounds__(256) pool_kernel(const int* __restrict__ batch)
{
    int c = threadIdx.x;
    int r0 = blockIdx.x * 128;
    if (r0 >= NN) return;
    int r1 = min(r0 + 128, NN);
    int cur = batch[r0];
    float s = 0.f;
    int run = 0;
    for (int r = r0; r < r1; r++) {
        int b = batch[r];
        if (b != cur) {
            atomicAdd(&g_pool[cur * HID + c], s);
            if (c == 0) atomicAdd(&g_cnt[cur], (float)run);
            s = 0.f; run = 0; cur = b;
        }
        s += g_x[(size_t)r * HID + c];
        run++;
    }
    atomicAdd(&g_pool[cur * HID + c], s);
    if (c == 0) atomicAdd(&g_cnt[cur], (float)run);
}

// ---------------- head ----------------
__global__ void __launch_bounds__(256) head_kernel(
    const float* __restrict__ hW, const float* __restrict__ hb,
    float* __restrict__ out)
{
    __shared__ float red[8];
    int g = blockIdx.x;
    int c = threadIdx.x;
    float s = g_pool[g * HID + c];
    float ct = fmaxf(g_cnt[g], 1.f);
    float p = (s / ct) * hW[c] + s * hW[HID + c];
#pragma unroll
    for (int off = 16; off; off >>= 1) p += __shfl_xor_sync(0xffffffffu, p, off);
    if ((c & 31) == 0) red[c >> 5] = p;
    __syncthreads();
    if (c == 0) {
        float t = 0.f;
#pragma unroll
        for (int i = 0; i < 8; i++) t += red[i];
        out[g] = t + hb[0];
    }
}

// ---------------- host ----------------
extern "C" void kernel_launch(void* const* d_in, const int* in_sizes, int n_in,
                              void* d_out, int out_size)
{
    const float* node_features = (const float*)d_in[0];
    const int*   edge_index    = (const int*)d_in[1];
    const float* edge_attr     = (const float*)d_in[2];
    const int*   batch         = (const int*)d_in[3];
    const float* proj_W        = (const float*)d_in[4];
    const float* proj_b        = (const float*)d_in[5];
    const float* Wq            = (const float*)d_in[6];
    const float* bq            = (const float*)d_in[7];
    const float* Wk            = (const float*)d_in[8];
    const float* bk            = (const float*)d_in[9];
    const float* Wv            = (const float*)d_in[10];
    const float* bv            = (const float*)d_in[11];
    const float* We            = (const float*)d_in[12];
    const float* be            = (const float*)d_in[13];
    const float* Wskip         = (const float*)d_in[14];
    const float* bskip         = (const float*)d_in[15];
    const float* Wbeta         = (const float*)d_in[16];
    const float* bng           = (const float*)d_in[17];
    const float* bnb           = (const float*)d_in[18];
    const float* headW         = (const float*)d_in[19];
    const float* headb         = (const float*)d_in[20];
    float* out = (float*)d_out;

    float *px, *pnf;
    cudaGetSymbolAddress((void**)&px,  g_x);
    cudaGetSymbolAddress((void**)&pnf, g_nf);

    // --- CSR by dst (edges identical for all layers) ---
    clear_deg_kernel<<<(NN + 255) / 256, 256>>>();
    hist_kernel<<<(NE + 255) / 256, 256>>>(edge_index);
    scan_kernel<<<1, SCAN_T>>>();
    scatter_kernel<<<(NE + 255) / 256, 256>>>(edge_index);

    dim3 gNode((NN + 127) / 128, 2);

    // input projection
    sgemm128<<<gNode, 256>>>(node_features, proj_W, proj_b, px, NN, IND, HID, HID);

    for (int l = 0; l < NL; l++) {
        clear_stats_kernel<<<1, 512>>>();

        const float* Ws[4] = { Wq + (size_t)l * HID * HID, Wk + (size_t)l * HID * HID,
                               Wv + (size_t)l * HID * HID, Wskip + (size_t)l * HID * HID };
        const float* bs[4] = { bq + l * HID, bk + l * HID, bv + l * HID, bskip + l * HID };
        for (int w = 0; w < 4; w++)
            sgemm128<<<gNode, 256>>>(px, Ws[w], bs[w], pnf + w * HID, NN, HID, HID, 1024);

        attn_kernel<<<(NN + 7) / 8, 256>>>(edge_attr,
                                           We + (size_t)l * ED * HID,
                                           be + l * HID,
                                           Wbeta + (size_t)l * 3 * HID);
        bnstats_kernel<<<(NN + 127) / 128, 256>>>();
        bnapply_kernel<<<(NN * HID + 255) / 256, 256>>>(bng + l * HID, bnb + l * HID);
    }

    clear_pool_kernel<<<(NG * HID + 255) / 256, 256>>>();
    pool_kernel<<<(NN + 127) / 128, 256>>>(batch);
    head_kernel<<<NG, 256>>>(headW, headb, out);
}

// round 5
// speedup vs baseline: 1.7440x; 1.3444x over previous
#include <cuda_runtime.h>
#include <cuda_bf16.h>
#include <math.h>
#include <stdint.h>

#define NN   50000
#define NE   500000
#define IND  64
#define ED   16
#define HID  256
#define NH   4
#define NL   4
#define NG   64
#define BN_EPS 1e-5f

#define RT_TILES 391                 // ceil(NN/128)
#define PAD_ROWS (RT_TILES * 128)    // 50048

// ---------------- scratch (static __device__ arrays; no allocation) ----------------
__device__ __align__(16) float g_x[(size_t)NN * HID];     // current node features
__device__ __align__(16) float g_nf[(size_t)NN * 1024];   // q|k|v|skip per node (stride 1024)
__device__ __align__(16) float g_attn[(size_t)NN * HID];  // post-attention features
__device__ float g_stats[2 * HID];
__device__ float g_pool[NG * HID];
__device__ float g_cnt[NG];
// CSR by destination
__device__ int  g_deg[NN];
__device__ int  g_rowptr[NN + 1];
__device__ int  g_cursor[NN];
__device__ __align__(8) int2 g_adj[NE];
// bf16-split GEMM operands
__device__ __align__(16) __nv_bfloat16 g_ahi[(size_t)PAD_ROWS * HID];  // x hi, row-major
__device__ __align__(16) __nv_bfloat16 g_alo[(size_t)PAD_ROWS * HID];  // x lo
__device__ __align__(16) __nv_bfloat16 g_whi[(size_t)NL * 4 * HID * HID]; // W^T: [l][w][n][k]
__device__ __align__(16) __nv_bfloat16 g_wlo[(size_t)NL * 4 * HID * HID];

// ================= CSR build =================
__global__ void __launch_bounds__(256) clear_deg_kernel()
{
    int i = blockIdx.x * 256 + threadIdx.x;
    if (i < NN) g_deg[i] = 0;
}
__global__ void __launch_bounds__(256) hist_kernel(const int* __restrict__ ei)
{
    int i = blockIdx.x * 256 + threadIdx.x;
    if (i < NE) atomicAdd(&g_deg[ei[NE + i]], 1);
}
#define SCAN_T 1024
#define SCAN_ITEMS ((NN + SCAN_T - 1) / SCAN_T)
__global__ void __launch_bounds__(SCAN_T) scan_kernel()
{
    __shared__ int wsum[32];
    int t = threadIdx.x;
    int lo = t * SCAN_ITEMS;
    int hi = min(lo + SCAN_ITEMS, NN);
    int s = 0;
    for (int i = lo; i < hi; i++) s += g_deg[i];
    int lane = t & 31, w = t >> 5;
    int v = s;
#pragma unroll
    for (int o = 1; o < 32; o <<= 1) {
        int u = __shfl_up_sync(0xffffffffu, v, o);
        if (lane >= o) v += u;
    }
    if (lane == 31) wsum[w] = v;
    __syncthreads();
    if (w == 0) {
        int x = wsum[lane];
#pragma unroll
        for (int o = 1; o < 32; o <<= 1) {
            int u = __shfl_up_sync(0xffffffffu, x, o);
            if (lane >= o) x += u;
        }
        wsum[lane] = x;
    }
    __syncthreads();
    int excl = v - s + (w ? wsum[w - 1] : 0);
    int run = excl;
    for (int i = lo; i < hi; i++) {
        g_rowptr[i] = run;
        g_cursor[i] = run;
        run += g_deg[i];
    }
    if (t == SCAN_T - 1) g_rowptr[NN] = excl + s;
}
__global__ void __launch_bounds__(256) scatter_kernel(const int* __restrict__ ei)
{
    int i = blockIdx.x * 256 + threadIdx.x;
    if (i < NE) {
        int dst = ei[NE + i];
        int pos = atomicAdd(&g_cursor[dst], 1);
        g_adj[pos] = make_int2(ei[i], i);
    }
}

// ================= misc clears =================
__global__ void __launch_bounds__(512) clear_stats_kernel() { g_stats[threadIdx.x] = 0.f; }
__global__ void __launch_bounds__(256) clear_pool_kernel()
{
    int i = blockIdx.x * 256 + threadIdx.x;
    if (i < NG * HID) g_pool[i] = 0.f;
    if (i < NG) g_cnt[i] = 0.f;
}

// ================= weight prep: transpose [K][N]->[N][K] + bf16 split (once per call) =================
__global__ void __launch_bounds__(256) convert_w_kernel(
    const float* __restrict__ Wq, const float* __restrict__ Wk,
    const float* __restrict__ Wv, const float* __restrict__ Wskip)
{
    int idx = blockIdx.x * 256 + threadIdx.x;   // over NL*4*256*256, output-indexed
    int k = idx & 255;
    int n = (idx >> 8) & 255;
    int w = (idx >> 16) & 3;
    int l = idx >> 18;
    const float* W = (w == 0) ? Wq : (w == 1) ? Wk : (w == 2) ? Wv : Wskip;
    float val = W[((size_t)l * 256 + k) * 256 + n];
    __nv_bfloat16 hi = __float2bfloat16(val);
    __nv_bfloat16 lo = __float2bfloat16(val - __bfloat162float(hi));
    g_whi[idx] = hi;
    g_wlo[idx] = lo;
}

// ================= per-layer x prep: bf16 split (row-major, rows padded with zeros) =================
__global__ void __launch_bounds__(256) convert_x_kernel()
{
    size_t idx = (size_t)blockIdx.x * 256 + threadIdx.x;   // over PAD_ROWS*256
    int r = (int)(idx >> 8);
    float val = (r < NN) ? g_x[idx] : 0.f;
    __nv_bfloat16 hi = __float2bfloat16(val);
    __nv_bfloat16 lo = __float2bfloat16(val - __bfloat162float(hi));
    g_ahi[idx] = hi;
    g_alo[idx] = lo;
}

// ================= mma.sync bf16 GEMM =================
// grid (391, 4): rowtile 128, w = blockIdx.y. Block tile 128m x 256n, BK=64.
// 8 warps in 2(m) x 4(n); warp tile 64x64. 3 passes: hi*hi, lo*hi, hi*lo.
// A smem [128][72] bf16 (pad for conflict-free frag loads); B smem [256][72].
#define APAD 72
#define ASMEM_ELEMS (128 * APAD)
#define BSMEM_ELEMS (256 * APAD)
#define GEMM_SMEM ((ASMEM_ELEMS + BSMEM_ELEMS) * 2)

__device__ __forceinline__ void mma16816(float* c, const uint32_t* a, uint32_t b0, uint32_t b1) {
    asm volatile("mma.sync.aligned.m16n8k16.row.col.f32.bf16.bf16.f32 "
                 "{%0,%1,%2,%3}, {%4,%5,%6,%7}, {%8,%9}, {%0,%1,%2,%3};"
                 : "+f"(c[0]), "+f"(c[1]), "+f"(c[2]), "+f"(c[3])
                 : "r"(a[0]), "r"(a[1]), "r"(a[2]), "r"(a[3]), "r"(b0), "r"(b1));
}

__global__ void __launch_bounds__(256, 1) mmagemm_kernel(
    int l, const float* __restrict__ b0p, const float* __restrict__ b1p,
    const float* __restrict__ b2p, const float* __restrict__ b3p)
{
    extern __shared__ __align__(16) __nv_bfloat16 sm[];
    __nv_bfloat16* sA = sm;                   // [128][APAD]
    __nv_bfloat16* sB = sm + ASMEM_ELEMS;     // [256][APAD]

    const int tid  = threadIdx.x;
    const int lane = tid & 31;
    const int wid  = tid >> 5;
    const int gid  = lane >> 2;      // 0..7
    const int tig  = lane & 3;       // 0..3
    const int rt   = blockIdx.x;
    const int w    = blockIdx.y;
    const int m0   = (wid >> 2) * 64;
    const int n0   = (wid & 3) * 64;

    float acc[4][8][4];
#pragma unroll
    for (int i = 0; i < 4; i++)
#pragma unroll
        for (int j = 0; j < 8; j++)
#pragma unroll
            for (int t = 0; t < 4; t++) acc[i][j][t] = 0.f;

    const size_t aoff = (size_t)rt * 128 * HID;
    const size_t boff = (size_t)(l * 4 + w) * HID * HID;

#pragma unroll 1
    for (int pass = 0; pass < 3; pass++) {
        const __nv_bfloat16* Ag = ((pass == 1) ? g_alo : g_ahi) + aoff;
        const __nv_bfloat16* Bg = ((pass == 2) ? g_wlo : g_whi) + boff;
#pragma unroll 1
        for (int kt = 0; kt < 4; kt++) {
            const int kbase = kt * 64;
            __syncthreads();
            // copy A: 128 rows x 64 bf16 (1024 uint4)
#pragma unroll
            for (int it = 0; it < 4; it++) {
                int e = tid + it * 256;
                int row = e >> 3, kg = e & 7;
                uint4 v = *(const uint4*)(Ag + (size_t)row * HID + kbase + kg * 8);
                *(uint4*)(sA + row * APAD + kg * 8) = v;
            }
            // copy B: 256 rows(n) x 64 bf16 (2048 uint4)
#pragma unroll
            for (int it = 0; it < 8; it++) {
                int e = tid + it * 256;
                int row = e >> 3, kg = e & 7;
                uint4 v = *(const uint4*)(Bg + (size_t)row * HID + kbase + kg * 8);
                *(uint4*)(sB + row * APAD + kg * 8) = v;
            }
            __syncthreads();

#pragma unroll
            for (int kk = 0; kk < 4; kk++) {
                const int k0 = kk * 16;
                uint32_t af[4][4];
#pragma unroll
                for (int i = 0; i < 4; i++) {
                    const __nv_bfloat16* base = sA + (m0 + i * 16 + gid) * APAD + k0 + 2 * tig;
                    af[i][0] = *(const uint32_t*)(base);
                    af[i][1] = *(const uint32_t*)(base + 8 * APAD);
                    af[i][2] = *(const uint32_t*)(base + 8);
                    af[i][3] = *(const uint32_t*)(base + 8 * APAD + 8);
                }
#pragma unroll
                for (int j = 0; j < 8; j++) {
                    const __nv_bfloat16* bb = sB + (n0 + j * 8 + gid) * APAD + k0 + 2 * tig;
                    uint32_t b0 = *(const uint32_t*)(bb);
                    uint32_t b1 = *(const uint32_t*)(bb + 8);
#pragma unroll
                    for (int i = 0; i < 4; i++)
                        mma16816(acc[i][j], af[i], b0, b1);
                }
            }
        }
    }

    // epilogue: g_nf[node][w*256 + col] = acc + bias
    const float* bias = (w == 0) ? b0p : (w == 1) ? b1p : (w == 2) ? b2p : b3p;
#pragma unroll
    for (int i = 0; i < 4; i++) {
        int node0 = rt * 128 + m0 + i * 16 + gid;
#pragma unroll
        for (int j = 0; j < 8; j++) {
            int col = n0 + j * 8 + 2 * tig;
            float2 bv = *(const float2*)(bias + col);
            if (node0 < NN) {
                float2 st = make_float2(acc[i][j][0] + bv.x, acc[i][j][1] + bv.y);
                *(float2*)(g_nf + (size_t)node0 * 1024 + w * 256 + col) = st;
            }
            int node1 = node0 + 8;
            if (node1 < NN) {
                float2 st = make_float2(acc[i][j][2] + bv.x, acc[i][j][3] + bv.y);
                *(float2*)(g_nf + (size_t)node1 * 1024 + w * 256 + col) = st;
            }
        }
    }
}

// ---------------- fp32 GEMM (input projection only, K=64) ----------------
__global__ void __launch_bounds__(256) sgemm128(
    const float* __restrict__ A, const float* __restrict__ B,
    const float* __restrict__ bias, float* __restrict__ C,
    int M, int K, int ldb, int ldc)
{
    __shared__ __align__(16) float As[8][128];
    __shared__ __align__(16) float Bs[8][128];

    const int tid = threadIdx.x;
    const int tx = tid & 15;
    const int ty = tid >> 4;
    const int row0 = blockIdx.x * 128;
    const int col0 = blockIdx.y * 128;

    const int arow = tid >> 1;
    const int akk  = (tid & 1) * 4;
    const int brow = tid >> 5;
    const int bcol = (tid & 31) * 4;

    float acc[8][8];
#pragma unroll
    for (int i = 0; i < 8; i++)
#pragma unroll
        for (int j = 0; j < 8; j++) acc[i][j] = 0.f;

    for (int kt = 0; kt < K; kt += 8) {
        float4 av = make_float4(0.f, 0.f, 0.f, 0.f);
        int r = row0 + arow;
        if (r < M) av = *(const float4*)(A + (size_t)r * K + kt + akk);
        As[akk + 0][arow] = av.x; As[akk + 1][arow] = av.y;
        As[akk + 2][arow] = av.z; As[akk + 3][arow] = av.w;

        float4 bv = *(const float4*)(B + (size_t)(kt + brow) * ldb + col0 + bcol);
        *(float4*)(&Bs[brow][bcol]) = bv;

        __syncthreads();
#pragma unroll
        for (int k = 0; k < 8; k++) {
            float ra[8], rb[8];
            *(float4*)(ra)     = *(const float4*)(&As[k][ty * 8]);
            *(float4*)(ra + 4) = *(const float4*)(&As[k][ty * 8 + 4]);
            *(float4*)(rb)     = *(const float4*)(&Bs[k][tx * 8]);
            *(float4*)(rb + 4) = *(const float4*)(&Bs[k][tx * 8 + 4]);
#pragma unroll
            for (int i = 0; i < 8; i++)
#pragma unroll
                for (int j = 0; j < 8; j++) acc[i][j] += ra[i] * rb[j];
        }
        __syncthreads();
    }

    float bvals[8];
#pragma unroll
    for (int j = 0; j < 8; j++) bvals[j] = bias[col0 + tx * 8 + j];

#pragma unroll
    for (int i = 0; i < 8; i++) {
        int r = row0 + ty * 8 + i;
        if (r < M) {
            float v[8];
#pragma unroll
            for (int j = 0; j < 8; j++) v[j] = acc[i][j] + bvals[j];
            float* cp = C + (size_t)r * ldc + col0 + tx * 8;
            *(float4*)(cp)     = *(float4*)(v);
            *(float4*)(cp + 4) = *(float4*)(v + 4);
        }
    }
}

// ================= fused attention: one warp per dst node, online softmax =================
__global__ void __launch_bounds__(256) attn_kernel(
    const float* __restrict__ eattr, const float* __restrict__ We,
    const float* __restrict__ be, const float* __restrict__ Wb)
{
    __shared__ __align__(16) float sWe[ED][HID];
    __shared__ float sbe[HID];

    for (int i = threadIdx.x; i < ED * HID; i += 256)
        sWe[i >> 8][i & 255] = We[i];
    if (threadIdx.x < HID) sbe[threadIdx.x] = be[threadIdx.x];
    __syncthreads();

    int n = blockIdx.x * 8 + (threadIdx.x >> 5);
    if (n >= NN) return;
    int lane = threadIdx.x & 31;
    int c0 = lane * 8;

    const float4* qp = (const float4*)(g_nf + (size_t)n * 1024 + c0);
    float4 q0 = qp[0], q1 = qp[1];

    float evb[8];
    {
        const float4* bp = (const float4*)(&sbe[c0]);
        float4 b0 = bp[0], b1 = bp[1];
        evb[0]=b0.x; evb[1]=b0.y; evb[2]=b0.z; evb[3]=b0.w;
        evb[4]=b1.x; evb[5]=b1.y; evb[6]=b1.z; evb[7]=b1.w;
    }

    float m = -INFINITY, d = 0.f;
    float acc[8] = {0.f,0.f,0.f,0.f,0.f,0.f,0.f,0.f};

    int beg = g_rowptr[n], end = g_rowptr[n + 1];
    for (int i = beg; i < end; i++) {
        int2 se = g_adj[i];
        int src = se.x, e = se.y;

        float ea[16];
        {
            const float4* eap = (const float4*)(eattr + (size_t)e * ED);
            float4 t0 = eap[0], t1 = eap[1], t2 = eap[2], t3 = eap[3];
            ea[0]=t0.x; ea[1]=t0.y; ea[2]=t0.z; ea[3]=t0.w;
            ea[4]=t1.x; ea[5]=t1.y; ea[6]=t1.z; ea[7]=t1.w;
            ea[8]=t2.x; ea[9]=t2.y; ea[10]=t2.z; ea[11]=t2.w;
            ea[12]=t3.x; ea[13]=t3.y; ea[14]=t3.z; ea[15]=t3.w;
        }
        float ev[8];
#pragma unroll
        for (int j = 0; j < 8; j++) ev[j] = evb[j];
#pragma unroll
        for (int f = 0; f < ED; f++) {
            const float4* wp = (const float4*)(&sWe[f][c0]);
            float4 w0 = wp[0], w1 = wp[1];
            float a = ea[f];
            ev[0] += a * w0.x; ev[1] += a * w0.y; ev[2] += a * w0.z; ev[3] += a * w0.w;
            ev[4] += a * w1.x; ev[5] += a * w1.y; ev[6] += a * w1.z; ev[7] += a * w1.w;
        }

        const float4* kp = (const float4*)(g_nf + (size_t)src * 1024 + HID + c0);
        const float4* vp = (const float4*)(g_nf + (size_t)src * 1024 + 2 * HID + c0);
        float4 k0 = kp[0], k1 = kp[1];
        float4 v0 = vp[0], v1 = vp[1];

        float s = q0.x * (k0.x + ev[0]) + q0.y * (k0.y + ev[1])
                + q0.z * (k0.z + ev[2]) + q0.w * (k0.w + ev[3])
                + q1.x * (k1.x + ev[4]) + q1.y * (k1.y + ev[5])
                + q1.z * (k1.z + ev[6]) + q1.w * (k1.w + ev[7]);
        s += __shfl_xor_sync(0xffffffffu, s, 4);
        s += __shfl_xor_sync(0xffffffffu, s, 2);
        s += __shfl_xor_sync(0xffffffffu, s, 1);
        float alpha = s * 0.125f;

        float mn = fmaxf(m, alpha);
        float scale = __expf(m - mn);
        float wgt = __expf(alpha - mn);
        d = d * scale + wgt;
        acc[0] = acc[0] * scale + wgt * (v0.x + ev[0]);
        acc[1] = acc[1] * scale + wgt * (v0.y + ev[1]);
        acc[2] = acc[2] * scale + wgt * (v0.z + ev[2]);
        acc[3] = acc[3] * scale + wgt * (v0.w + ev[3]);
        acc[4] = acc[4] * scale + wgt * (v1.x + ev[4]);
        acc[5] = acc[5] * scale + wgt * (v1.y + ev[5]);
        acc[6] = acc[6] * scale + wgt * (v1.z + ev[6]);
        acc[7] = acc[7] * scale + wgt * (v1.w + ev[7]);
        m = mn;
    }

    float inv = (d > 0.f) ? (1.f / d) : 0.f;
    float o[8];
#pragma unroll
    for (int j = 0; j < 8; j++) o[j] = acc[j] * inv;

    float sk[8];
    {
        const float4* sp = (const float4*)(g_nf + (size_t)n * 1024 + 3 * HID + c0);
        float4 s0 = sp[0], s1 = sp[1];
        sk[0]=s0.x; sk[1]=s0.y; sk[2]=s0.z; sk[3]=s0.w;
        sk[4]=s1.x; sk[5]=s1.y; sk[6]=s1.z; sk[7]=s1.w;
    }

    float p = 0.f;
#pragma unroll
    for (int j = 0; j < 8; j++) {
        int c = c0 + j;
        p += o[j] * (Wb[c] + Wb[2 * HID + c]) + sk[j] * (Wb[HID + c] - Wb[2 * HID + c]);
    }
#pragma unroll
    for (int off = 16; off; off >>= 1) p += __shfl_xor_sync(0xffffffffu, p, off);
    float beta = 1.f / (1.f + __expf(-p));

    float* op = g_attn + (size_t)n * HID + c0;
    float r[8];
#pragma unroll
    for (int j = 0; j < 8; j++) r[j] = beta * sk[j] + (1.f - beta) * o[j];
    *(float4*)(op)     = *(float4*)(r);
    *(float4*)(op + 4) = *(float4*)(r + 4);
}

// ---------------- batchnorm stats ----------------
__global__ void __launch_bounds__(256) bnstats_kernel()
{
    int c = threadIdx.x;
    int r0 = blockIdx.x * 128;
    int r1 = min(r0 + 128, NN);
    float s = 0.f, s2 = 0.f;
    for (int r = r0; r < r1; r++) {
        float v = g_attn[(size_t)r * HID + c];
        s += v; s2 += v * v;
    }
    atomicAdd(&g_stats[c], s);
    atomicAdd(&g_stats[HID + c], s2);
}

// ---------------- batchnorm apply + LeakyReLU ----------------
__global__ void __launch_bounds__(256) bnapply_kernel(
    const float* __restrict__ gamma, const float* __restrict__ bbeta)
{
    size_t idx = (size_t)blockIdx.x * blockDim.x + threadIdx.x;
    if (idx >= (size_t)NN * HID) return;
    int c = (int)(idx & (HID - 1));
    const float invN = 1.f / (float)NN;
    float mu = g_stats[c] * invN;
    float var = g_stats[HID + c] * invN - mu * mu;
    var = fmaxf(var, 0.f);
    float y = (g_attn[idx] - mu) * rsqrtf(var + BN_EPS) * gamma[c] + bbeta[c];
    g_x[idx] = (y >= 0.f) ? y : 0.1f * y;
}

// ---------------- pooling ----------------
__global__ void __launch_bounds__(256) pool_kernel(const int* __restrict__ batch)
{
    int c = threadIdx.x;
    int r0 = blockIdx.x * 128;
    if (r0 >= NN) return;
    int r1 = min(r0 + 128, NN);
    int cur = batch[r0];
    float s = 0.f;
    int run = 0;
    for (int r = r0; r < r1; r++) {
        int b = batch[r];
        if (b != cur) {
            atomicAdd(&g_pool[cur * HID + c], s);
            if (c == 0) atomicAdd(&g_cnt[cur], (float)run);
            s = 0.f; run = 0; cur = b;
        }
        s += g_x[(size_t)r * HID + c];
        run++;
    }
    atomicAdd(&g_pool[cur * HID + c], s);
    if (c == 0) atomicAdd(&g_cnt[cur], (float)run);
}

// ---------------- head ----------------
__global__ void __launch_bounds__(256) head_kernel(
    const float* __restrict__ hW, const float* __restrict__ hb,
    float* __restrict__ out)
{
    __shared__ float red[8];
    int g = blockIdx.x;
    int c = threadIdx.x;
    float s = g_pool[g * HID + c];
    float ct = fmaxf(g_cnt[g], 1.f);
    float p = (s / ct) * hW[c] + s * hW[HID + c];
#pragma unroll
    for (int off = 16; off; off >>= 1) p += __shfl_xor_sync(0xffffffffu, p, off);
    if ((c & 31) == 0) red[c >> 5] = p;
    __syncthreads();
    if (c == 0) {
        float t = 0.f;
#pragma unroll
        for (int i = 0; i < 8; i++) t += red[i];
        out[g] = t + hb[0];
    }
}

// ---------------- host ----------------
#define GEMM_SMEM_BYTES ((128 * 72 + 256 * 72) * 2)

extern "C" void kernel_launch(void* const* d_in, const int* in_sizes, int n_in,
                              void* d_out, int out_size)
{
    const float* node_features = (const float*)d_in[0];
    const int*   edge_index    = (const int*)d_in[1];
    const float* edge_attr     = (const float*)d_in[2];
    const int*   batch         = (const int*)d_in[3];
    const float* proj_W        = (const float*)d_in[4];
    const float* proj_b        = (const float*)d_in[5];
    const float* Wq            = (const float*)d_in[6];
    const float* bq            = (const float*)d_in[7];
    const float* Wk            = (const float*)d_in[8];
    const float* bk            = (const float*)d_in[9];
    const float* Wv            = (const float*)d_in[10];
    const float* bv            = (const float*)d_in[11];
    const float* We            = (const float*)d_in[12];
    const float* be            = (const float*)d_in[13];
    const float* Wskip         = (const float*)d_in[14];
    const float* bskip         = (const float*)d_in[15];
    const float* Wbeta         = (const float*)d_in[16];
    const float* bng           = (const float*)d_in[17];
    const float* bnb           = (const float*)d_in[18];
    const float* headW         = (const float*)d_in[19];
    const float* headb         = (const float*)d_in[20];
    float* out = (float*)d_out;

    cudaFuncSetAttribute(mmagemm_kernel, cudaFuncAttributeMaxDynamicSharedMemorySize, GEMM_SMEM_BYTES);

    float* px;
    cudaGetSymbolAddress((void**)&px, g_x);

    // CSR by dst + weight prep (layer-invariant)
    clear_deg_kernel<<<(NN + 255) / 256, 256>>>();
    hist_kernel<<<(NE + 255) / 256, 256>>>(edge_index);
    scan_kernel<<<1, SCAN_T>>>();
    scatter_kernel<<<(NE + 255) / 256, 256>>>(edge_index);
    convert_w_kernel<<<(NL * 4 * 256 * 256) / 256, 256>>>(Wq, Wk, Wv, Wskip);

    // input projection (fp32 FFMA; K=64, small)
    dim3 gNode((NN + 127) / 128, 2);
    sgemm128<<<gNode, 256>>>(node_features, proj_W, proj_b, px, NN, IND, HID, HID);

    for (int l = 0; l < NL; l++) {
        clear_stats_kernel<<<1, 512>>>();
        convert_x_kernel<<<(PAD_ROWS * 256) / 256, 256>>>();
        mmagemm_kernel<<<dim3(RT_TILES, 4), 256, GEMM_SMEM_BYTES>>>(
            l, bq + l * HID, bk + l * HID, bv + l * HID, bskip + l * HID);
        attn_kernel<<<(NN + 7) / 8, 256>>>(edge_attr,
                                           We + (size_t)l * ED * HID,
                                           be + l * HID,
                                           Wbeta + (size_t)l * 3 * HID);
        bnstats_kernel<<<(NN + 127) / 128, 256>>>();
        bnapply_kernel<<<(NN * HID + 255) / 256, 256>>>(bng + l * HID, bnb + l * HID);
    }

    clear_pool_kernel<<<(NG * HID + 255) / 256, 256>>>();
    pool_kernel<<<(NN + 127) / 128, 256>>>(batch);
    head_kernel<<<NG, 256>>>(headW, headb, out);
}

// round 6
// speedup vs baseline: 1.7874x; 1.0248x over previous
#include <cuda_runtime.h>
#include <cuda_bf16.h>
#include <math.h>
#include <stdint.h>

#define NN   50000
#define NE   500000
#define IND  64
#define ED   16
#define HID  256
#define NH   4
#define NL   4
#define NG   64
#define BN_EPS 1e-5f

#define RT_TILES 391                 // ceil(NN/128)
#define PAD_ROWS (RT_TILES * 128)    // 50048

// ---------------- scratch (static __device__ arrays; no allocation) ----------------
__device__ __align__(16) float g_x[(size_t)NN * HID];     // current node features
__device__ __align__(16) float g_kv[(size_t)NN * 512];    // k|v per node (gathered; L2-resident, 100MB)
__device__ __align__(16) float g_qs[(size_t)NN * 512];    // q|skip per node (streamed)
__device__ __align__(16) float g_attn[(size_t)NN * HID];  // post-attention features
__device__ float g_stats[2 * HID];
__device__ float g_pool[NG * HID];
__device__ float g_cnt[NG];
// CSR by destination
__device__ int  g_deg[NN];
__device__ int  g_rowptr[NN + 1];
__device__ int  g_cursor[NN];
__device__ __align__(8) int2 g_adj[NE];
// bf16-split GEMM operands
__device__ __align__(16) __nv_bfloat16 g_ahi[(size_t)PAD_ROWS * HID];
__device__ __align__(16) __nv_bfloat16 g_alo[(size_t)PAD_ROWS * HID];
__device__ __align__(16) __nv_bfloat16 g_whi[(size_t)NL * 4 * HID * HID]; // W^T: [l][w][n][k]
__device__ __align__(16) __nv_bfloat16 g_wlo[(size_t)NL * 4 * HID * HID];

// ================= CSR build =================
__global__ void __launch_bounds__(256) clear_deg_kernel()
{
    int i = blockIdx.x * 256 + threadIdx.x;
    if (i < NN) g_deg[i] = 0;
}
__global__ void __launch_bounds__(256) hist_kernel(const int* __restrict__ ei)
{
    int i = blockIdx.x * 256 + threadIdx.x;
    if (i < NE) atomicAdd(&g_deg[ei[NE + i]], 1);
}
#define SCAN_T 1024
#define SCAN_ITEMS ((NN + SCAN_T - 1) / SCAN_T)
__global__ void __launch_bounds__(SCAN_T) scan_kernel()
{
    __shared__ int wsum[32];
    int t = threadIdx.x;
    int lo = t * SCAN_ITEMS;
    int hi = min(lo + SCAN_ITEMS, NN);
    int s = 0;
    for (int i = lo; i < hi; i++) s += g_deg[i];
    int lane = t & 31, w = t >> 5;
    int v = s;
#pragma unroll
    for (int o = 1; o < 32; o <<= 1) {
        int u = __shfl_up_sync(0xffffffffu, v, o);
        if (lane >= o) v += u;
    }
    if (lane == 31) wsum[w] = v;
    __syncthreads();
    if (w == 0) {
        int x = wsum[lane];
#pragma unroll
        for (int o = 1; o < 32; o <<= 1) {
            int u = __shfl_up_sync(0xffffffffu, x, o);
            if (lane >= o) x += u;
        }
        wsum[lane] = x;
    }
    __syncthreads();
    int excl = v - s + (w ? wsum[w - 1] : 0);
    int run = excl;
    for (int i = lo; i < hi; i++) {
        g_rowptr[i] = run;
        g_cursor[i] = run;
        run += g_deg[i];
    }
    if (t == SCAN_T - 1) g_rowptr[NN] = excl + s;
}
__global__ void __launch_bounds__(256) scatter_kernel(const int* __restrict__ ei)
{
    int i = blockIdx.x * 256 + threadIdx.x;
    if (i < NE) {
        int dst = ei[NE + i];
        int pos = atomicAdd(&g_cursor[dst], 1);
        g_adj[pos] = make_int2(ei[i], i);
    }
}

// ================= misc clears =================
__global__ void __launch_bounds__(512) clear_stats_kernel() { g_stats[threadIdx.x] = 0.f; }
__global__ void __launch_bounds__(256) clear_pool_kernel()
{
    int i = blockIdx.x * 256 + threadIdx.x;
    if (i < NG * HID) g_pool[i] = 0.f;
    if (i < NG) g_cnt[i] = 0.f;
}

// ================= weight prep: transpose [K][N]->[N][K] + bf16 split =================
__global__ void __launch_bounds__(256) convert_w_kernel(
    const float* __restrict__ Wq, const float* __restrict__ Wk,
    const float* __restrict__ Wv, const float* __restrict__ Wskip)
{
    int idx = blockIdx.x * 256 + threadIdx.x;   // over NL*4*256*256, output-indexed
    int k = idx & 255;
    int n = (idx >> 8) & 255;
    int w = (idx >> 16) & 3;
    int l = idx >> 18;
    const float* W = (w == 0) ? Wq : (w == 1) ? Wk : (w == 2) ? Wv : Wskip;
    float val = W[((size_t)l * 256 + k) * 256 + n];
    __nv_bfloat16 hi = __float2bfloat16(val);
    __nv_bfloat16 lo = __float2bfloat16(val - __bfloat162float(hi));
    g_whi[idx] = hi;
    g_wlo[idx] = lo;
}

// ================= initial x prep: bf16 split (padded rows zero) =================
__global__ void __launch_bounds__(256) convert_x_kernel()
{
    size_t idx = (size_t)blockIdx.x * 256 + threadIdx.x;   // over PAD_ROWS*256
    int r = (int)(idx >> 8);
    float val = (r < NN) ? g_x[idx] : 0.f;
    __nv_bfloat16 hi = __float2bfloat16(val);
    __nv_bfloat16 lo = __float2bfloat16(val - __bfloat162float(hi));
    g_ahi[idx] = hi;
    g_alo[idx] = lo;
}

// ================= mma.sync bf16 GEMM =================
// grid (391, 4): rowtile 128, w = blockIdx.y. Block tile 128m x 256n, BK=64.
// 8 warps 2(m) x 4(n); warp tile 64x64. 3 passes: hi*hi, lo*hi, hi*lo.
#define APAD 72
#define ASMEM_ELEMS (128 * APAD)
#define BSMEM_ELEMS (256 * APAD)

__device__ __forceinline__ void mma16816(float* c, const uint32_t* a, uint32_t b0, uint32_t b1) {
    asm volatile("mma.sync.aligned.m16n8k16.row.col.f32.bf16.bf16.f32 "
                 "{%0,%1,%2,%3}, {%4,%5,%6,%7}, {%8,%9}, {%0,%1,%2,%3};"
                 : "+f"(c[0]), "+f"(c[1]), "+f"(c[2]), "+f"(c[3])
                 : "r"(a[0]), "r"(a[1]), "r"(a[2]), "r"(a[3]), "r"(b0), "r"(b1));
}

__global__ void __launch_bounds__(256, 1) mmagemm_kernel(
    int l, const float* __restrict__ b0p, const float* __restrict__ b1p,
    const float* __restrict__ b2p, const float* __restrict__ b3p)
{
    extern __shared__ __align__(16) __nv_bfloat16 sm[];
    __nv_bfloat16* sA = sm;                   // [128][APAD]
    __nv_bfloat16* sB = sm + ASMEM_ELEMS;     // [256][APAD]

    const int tid  = threadIdx.x;
    const int lane = tid & 31;
    const int wid  = tid >> 5;
    const int gid  = lane >> 2;
    const int tig  = lane & 3;
    const int rt   = blockIdx.x;
    const int w    = blockIdx.y;
    const int m0   = (wid >> 2) * 64;
    const int n0   = (wid & 3) * 64;

    float acc[4][8][4];
#pragma unroll
    for (int i = 0; i < 4; i++)
#pragma unroll
        for (int j = 0; j < 8; j++)
#pragma unroll
            for (int t = 0; t < 4; t++) acc[i][j][t] = 0.f;

    const size_t aoff = (size_t)rt * 128 * HID;
    const size_t boff = (size_t)(l * 4 + w) * HID * HID;

#pragma unroll 1
    for (int pass = 0; pass < 3; pass++) {
        const __nv_bfloat16* Ag = ((pass == 1) ? g_alo : g_ahi) + aoff;
        const __nv_bfloat16* Bg = ((pass == 2) ? g_wlo : g_whi) + boff;
#pragma unroll 1
        for (int kt = 0; kt < 4; kt++) {
            const int kbase = kt * 64;
            __syncthreads();
#pragma unroll
            for (int it = 0; it < 4; it++) {
                int e = tid + it * 256;
                int row = e >> 3, kg = e & 7;
                uint4 v = *(const uint4*)(Ag + (size_t)row * HID + kbase + kg * 8);
                *(uint4*)(sA + row * APAD + kg * 8) = v;
            }
#pragma unroll
            for (int it = 0; it < 8; it++) {
                int e = tid + it * 256;
                int row = e >> 3, kg = e & 7;
                uint4 v = *(const uint4*)(Bg + (size_t)row * HID + kbase + kg * 8);
                *(uint4*)(sB + row * APAD + kg * 8) = v;
            }
            __syncthreads();

#pragma unroll
            for (int kk = 0; kk < 4; kk++) {
                const int k0 = kk * 16;
                uint32_t af[4][4];
#pragma unroll
                for (int i = 0; i < 4; i++) {
                    const __nv_bfloat16* base = sA + (m0 + i * 16 + gid) * APAD + k0 + 2 * tig;
                    af[i][0] = *(const uint32_t*)(base);
                    af[i][1] = *(const uint32_t*)(base + 8 * APAD);
                    af[i][2] = *(const uint32_t*)(base + 8);
                    af[i][3] = *(const uint32_t*)(base + 8 * APAD + 8);
                }
#pragma unroll
                for (int j = 0; j < 8; j++) {
                    const __nv_bfloat16* bb = sB + (n0 + j * 8 + gid) * APAD + k0 + 2 * tig;
                    uint32_t b0 = *(const uint32_t*)(bb);
                    uint32_t b1 = *(const uint32_t*)(bb + 8);
#pragma unroll
                    for (int i = 0; i < 4; i++)
                        mma16816(acc[i][j], af[i], b0, b1);
                }
            }
        }
    }

    // epilogue routed by w: q->g_qs[:,0:256], k->g_kv[:,0:256], v->g_kv[:,256:512], skip->g_qs[:,256:512]
    const float* bias = (w == 0) ? b0p : (w == 1) ? b1p : (w == 2) ? b2p : b3p;
    float* dstbase = (w == 0) ? g_qs : (w == 1) ? g_kv : (w == 2) ? g_kv : g_qs;
    const int coff = (w == 0 || w == 1) ? 0 : 256;
#pragma unroll
    for (int i = 0; i < 4; i++) {
        int node0 = rt * 128 + m0 + i * 16 + gid;
#pragma unroll
        for (int j = 0; j < 8; j++) {
            int col = n0 + j * 8 + 2 * tig;
            float2 bv = *(const float2*)(bias + col);
            if (node0 < NN) {
                float2 st = make_float2(acc[i][j][0] + bv.x, acc[i][j][1] + bv.y);
                *(float2*)(dstbase + (size_t)node0 * 512 + coff + col) = st;
            }
            int node1 = node0 + 8;
            if (node1 < NN) {
                float2 st = make_float2(acc[i][j][2] + bv.x, acc[i][j][3] + bv.y);
                *(float2*)(dstbase + (size_t)node1 * 512 + coff + col) = st;
            }
        }
    }
}

// ---------------- fp32 GEMM (input projection only, K=64) ----------------
__global__ void __launch_bounds__(256) sgemm128(
    const float* __restrict__ A, const float* __restrict__ B,
    const float* __restrict__ bias, float* __restrict__ C,
    int M, int K, int ldb, int ldc)
{
    __shared__ __align__(16) float As[8][128];
    __shared__ __align__(16) float Bs[8][128];

    const int tid = threadIdx.x;
    const int tx = tid & 15;
    const int ty = tid >> 4;
    const int row0 = blockIdx.x * 128;
    const int col0 = blockIdx.y * 128;

    const int arow = tid >> 1;
    const int akk  = (tid & 1) * 4;
    const int brow = tid >> 5;
    const int bcol = (tid & 31) * 4;

    float acc[8][8];
#pragma unroll
    for (int i = 0; i < 8; i++)
#pragma unroll
        for (int j = 0; j < 8; j++) acc[i][j] = 0.f;

    for (int kt = 0; kt < K; kt += 8) {
        float4 av = make_float4(0.f, 0.f, 0.f, 0.f);
        int r = row0 + arow;
        if (r < M) av = *(const float4*)(A + (size_t)r * K + kt + akk);
        As[akk + 0][arow] = av.x; As[akk + 1][arow] = av.y;
        As[akk + 2][arow] = av.z; As[akk + 3][arow] = av.w;

        float4 bv = *(const float4*)(B + (size_t)(kt + brow) * ldb + col0 + bcol);
        *(float4*)(&Bs[brow][bcol]) = bv;

        __syncthreads();
#pragma unroll
        for (int k = 0; k < 8; k++) {
            float ra[8], rb[8];
            *(float4*)(ra)     = *(const float4*)(&As[k][ty * 8]);
            *(float4*)(ra + 4) = *(const float4*)(&As[k][ty * 8 + 4]);
            *(float4*)(rb)     = *(const float4*)(&Bs[k][tx * 8]);
            *(float4*)(rb + 4) = *(const float4*)(&Bs[k][tx * 8 + 4]);
#pragma unroll
            for (int i = 0; i < 8; i++)
#pragma unroll
                for (int j = 0; j < 8; j++) acc[i][j] += ra[i] * rb[j];
        }
        __syncthreads();
    }

    float bvals[8];
#pragma unroll
    for (int j = 0; j < 8; j++) bvals[j] = bias[col0 + tx * 8 + j];

#pragma unroll
    for (int i = 0; i < 8; i++) {
        int r = row0 + ty * 8 + i;
        if (r < M) {
            float v[8];
#pragma unroll
            for (int j = 0; j < 8; j++) v[j] = acc[i][j] + bvals[j];
            float* cp = C + (size_t)r * ldc + col0 + tx * 8;
            *(float4*)(cp)     = *(float4*)(v);
            *(float4*)(cp + 4) = *(float4*)(v + 4);
        }
    }
}

// ================= fused attention: one warp per dst node, online softmax =================
__global__ void __launch_bounds__(256) attn_kernel(
    const float* __restrict__ eattr, const float* __restrict__ We,
    const float* __restrict__ be, const float* __restrict__ Wb)
{
    __shared__ __align__(16) float sWe[ED][HID];   // 16 KB
    __shared__ float sbe[HID];
    __shared__ float sWb1[HID];                    // Wb0 + Wb2
    __shared__ float sWb2[HID];                    // Wb1 - Wb2

    for (int i = threadIdx.x; i < ED * HID; i += 256)
        sWe[i >> 8][i & 255] = We[i];
    if (threadIdx.x < HID) {
        int c = threadIdx.x;
        sbe[c] = be[c];
        float w2 = Wb[2 * HID + c];
        sWb1[c] = Wb[c] + w2;
        sWb2[c] = Wb[HID + c] - w2;
    }
    __syncthreads();

    int n = blockIdx.x * 8 + (threadIdx.x >> 5);
    if (n >= NN) return;
    int lane = threadIdx.x & 31;
    int c0 = lane * 8;

    const float4* qp = (const float4*)(g_qs + (size_t)n * 512 + c0);
    float4 q0 = qp[0], q1 = qp[1];

    float evb[8];
    {
        const float4* bp = (const float4*)(&sbe[c0]);
        float4 b0 = bp[0], b1 = bp[1];
        evb[0]=b0.x; evb[1]=b0.y; evb[2]=b0.z; evb[3]=b0.w;
        evb[4]=b1.x; evb[5]=b1.y; evb[6]=b1.z; evb[7]=b1.w;
    }

    float m = -INFINITY, d = 0.f;
    float acc[8] = {0.f,0.f,0.f,0.f,0.f,0.f,0.f,0.f};

    int beg = g_rowptr[n], end = g_rowptr[n + 1];
    for (int i = beg; i < end; i++) {
        int2 se = g_adj[i];
        int src = se.x, e = se.y;

        float ea[16];
        {
            const float4* eap = (const float4*)(eattr + (size_t)e * ED);
            float4 t0 = eap[0], t1 = eap[1], t2 = eap[2], t3 = eap[3];
            ea[0]=t0.x; ea[1]=t0.y; ea[2]=t0.z; ea[3]=t0.w;
            ea[4]=t1.x; ea[5]=t1.y; ea[6]=t1.z; ea[7]=t1.w;
            ea[8]=t2.x; ea[9]=t2.y; ea[10]=t2.z; ea[11]=t2.w;
            ea[12]=t3.x; ea[13]=t3.y; ea[14]=t3.z; ea[15]=t3.w;
        }
        float ev[8];
#pragma unroll
        for (int j = 0; j < 8; j++) ev[j] = evb[j];
#pragma unroll
        for (int f = 0; f < ED; f++) {
            const float4* wp = (const float4*)(&sWe[f][c0]);
            float4 w0 = wp[0], w1 = wp[1];
            float a = ea[f];
            ev[0] += a * w0.x; ev[1] += a * w0.y; ev[2] += a * w0.z; ev[3] += a * w0.w;
            ev[4] += a * w1.x; ev[5] += a * w1.y; ev[6] += a * w1.z; ev[7] += a * w1.w;
        }

        const float4* kp = (const float4*)(g_kv + (size_t)src * 512 + c0);
        const float4* vp = (const float4*)(g_kv + (size_t)src * 512 + 256 + c0);
        float4 k0 = kp[0], k1 = kp[1];
        float4 v0 = vp[0], v1 = vp[1];

        float s = q0.x * (k0.x + ev[0]) + q0.y * (k0.y + ev[1])
                + q0.z * (k0.z + ev[2]) + q0.w * (k0.w + ev[3])
                + q1.x * (k1.x + ev[4]) + q1.y * (k1.y + ev[5])
                + q1.z * (k1.z + ev[6]) + q1.w * (k1.w + ev[7]);
        s += __shfl_xor_sync(0xffffffffu, s, 4);
        s += __shfl_xor_sync(0xffffffffu, s, 2);
        s += __shfl_xor_sync(0xffffffffu, s, 1);
        float alpha = s * 0.125f;

        float mn = fmaxf(m, alpha);
        float scale = __expf(m - mn);
        float wgt = __expf(alpha - mn);
        d = d * scale + wgt;
        acc[0] = acc[0] * scale + wgt * (v0.x + ev[0]);
        acc[1] = acc[1] * scale + wgt * (v0.y + ev[1]);
        acc[2] = acc[2] * scale + wgt * (v0.z + ev[2]);
        acc[3] = acc[3] * scale + wgt * (v0.w + ev[3]);
        acc[4] = acc[4] * scale + wgt * (v1.x + ev[4]);
        acc[5] = acc[5] * scale + wgt * (v1.y + ev[5]);
        acc[6] = acc[6] * scale + wgt * (v1.z + ev[6]);
        acc[7] = acc[7] * scale + wgt * (v1.w + ev[7]);
        m = mn;
    }

    float inv = (d > 0.f) ? (1.f / d) : 0.f;
    float o[8];
#pragma unroll
    for (int j = 0; j < 8; j++) o[j] = acc[j] * inv;

    float sk[8];
    {
        const float4* sp = (const float4*)(g_qs + (size_t)n * 512 + 256 + c0);
        float4 s0 = sp[0], s1 = sp[1];
        sk[0]=s0.x; sk[1]=s0.y; sk[2]=s0.z; sk[3]=s0.w;
        sk[4]=s1.x; sk[5]=s1.y; sk[6]=s1.z; sk[7]=s1.w;
    }

    float p = 0.f;
#pragma unroll
    for (int j = 0; j < 8; j++) {
        int c = c0 + j;
        p += o[j] * sWb1[c] + sk[j] * sWb2[c];
    }
#pragma unroll
    for (int off = 16; off; off >>= 1) p += __shfl_xor_sync(0xffffffffu, p, off);
    float beta = 1.f / (1.f + __expf(-p));

    float* op = g_attn + (size_t)n * HID + c0;
    float r[8];
#pragma unroll
    for (int j = 0; j < 8; j++) r[j] = beta * sk[j] + (1.f - beta) * o[j];
    *(float4*)(op)     = *(float4*)(r);
    *(float4*)(op + 4) = *(float4*)(r + 4);
}

// ---------------- batchnorm stats ----------------
__global__ void __launch_bounds__(256) bnstats_kernel()
{
    int c = threadIdx.x;
    int r0 = blockIdx.x * 128;
    int r1 = min(r0 + 128, NN);
    float s = 0.f, s2 = 0.f;
    for (int r = r0; r < r1; r++) {
        float v = g_attn[(size_t)r * HID + c];
        s += v; s2 += v * v;
    }
    atomicAdd(&g_stats[c], s);
    atomicAdd(&g_stats[HID + c], s2);
}

// ---------------- batchnorm apply + LeakyReLU + bf16 split (fused) ----------------
__global__ void __launch_bounds__(256) bnapply_convert_kernel(
    const float* __restrict__ gamma, const float* __restrict__ bbeta, int do_convert)
{
    size_t idx = (size_t)blockIdx.x * blockDim.x + threadIdx.x;
    if (idx >= (size_t)NN * HID) return;
    int c = (int)(idx & (HID - 1));
    const float invN = 1.f / (float)NN;
    float mu = g_stats[c] * invN;
    float var = g_stats[HID + c] * invN - mu * mu;
    var = fmaxf(var, 0.f);
    float y = (g_attn[idx] - mu) * rsqrtf(var + BN_EPS) * gamma[c] + bbeta[c];
    y = (y >= 0.f) ? y : 0.1f * y;
    g_x[idx] = y;
    if (do_convert) {
        __nv_bfloat16 hi = __float2bfloat16(y);
        __nv_bfloat16 lo = __float2bfloat16(y - __bfloat162float(hi));
        g_ahi[idx] = hi;
        g_alo[idx] = lo;
    }
}

// ---------------- pooling ----------------
__global__ void __launch_bounds__(256) pool_kernel(const int* __restrict__ batch)
{
    int c = threadIdx.x;
    int r0 = blockIdx.x * 128;
    if (r0 >= NN) return;
    int r1 = min(r0 + 128, NN);
    int cur = batch[r0];
    float s = 0.f;
    int run = 0;
    for (int r = r0; r < r1; r++) {
        int b = batch[r];
        if (b != cur) {
            atomicAdd(&g_pool[cur * HID + c], s);
            if (c == 0) atomicAdd(&g_cnt[cur], (float)run);
            s = 0.f; run = 0; cur = b;
        }
        s += g_x[(size_t)r * HID + c];
        run++;
    }
    atomicAdd(&g_pool[cur * HID + c], s);
    if (c == 0) atomicAdd(&g_cnt[cur], (float)run);
}

// ---------------- head ----------------
__global__ void __launch_bounds__(256) head_kernel(
    const float* __restrict__ hW, const float* __restrict__ hb,
    float* __restrict__ out)
{
    __shared__ float red[8];
    int g = blockIdx.x;
    int c = threadIdx.x;
    float s = g_pool[g * HID + c];
    float ct = fmaxf(g_cnt[g], 1.f);
    float p = (s / ct) * hW[c] + s * hW[HID + c];
#pragma unroll
    for (int off = 16; off; off >>= 1) p += __shfl_xor_sync(0xffffffffu, p, off);
    if ((c & 31) == 0) red[c >> 5] = p;
    __syncthreads();
    if (c == 0) {
        float t = 0.f;
#pragma unroll
        for (int i = 0; i < 8; i++) t += red[i];
        out[g] = t + hb[0];
    }
}

// ---------------- host ----------------
#define GEMM_SMEM_BYTES ((128 * 72 + 256 * 72) * 2)

extern "C" void kernel_launch(void* const* d_in, const int* in_sizes, int n_in,
                              void* d_out, int out_size)
{
    const float* node_features = (const float*)d_in[0];
    const int*   edge_index    = (const int*)d_in[1];
    const float* edge_attr     = (const float*)d_in[2];
    const int*   batch         = (const int*)d_in[3];
    const float* proj_W        = (const float*)d_in[4];
    const float* proj_b        = (const float*)d_in[5];
    const float* Wq            = (const float*)d_in[6];
    const float* bq            = (const float*)d_in[7];
    const float* Wk            = (const float*)d_in[8];
    const float* bk            = (const float*)d_in[9];
    const float* Wv            = (const float*)d_in[10];
    const float* bv            = (const float*)d_in[11];
    const float* We            = (const float*)d_in[12];
    const float* be            = (const float*)d_in[13];
    const float* Wskip         = (const float*)d_in[14];
    const float* bskip         = (const float*)d_in[15];
    const float* Wbeta         = (const float*)d_in[16];
    const float* bng           = (const float*)d_in[17];
    const float* bnb           = (const float*)d_in[18];
    const float* headW         = (const float*)d_in[19];
    const float* headb         = (const float*)d_in[20];
    float* out = (float*)d_out;

    cudaFuncSetAttribute(mmagemm_kernel, cudaFuncAttributeMaxDynamicSharedMemorySize, GEMM_SMEM_BYTES);

    float* px;
    cudaGetSymbolAddress((void**)&px, g_x);

    // CSR by dst + weight prep (layer-invariant)
    clear_deg_kernel<<<(NN + 255) / 256, 256>>>();
    hist_kernel<<<(NE + 255) / 256, 256>>>(edge_index);
    scan_kernel<<<1, SCAN_T>>>();
    scatter_kernel<<<(NE + 255) / 256, 256>>>(edge_index);
    convert_w_kernel<<<(NL * 4 * 256 * 256) / 256, 256>>>(Wq, Wk, Wv, Wskip);

    // input projection (fp32 FFMA; K=64)
    dim3 gNode((NN + 127) / 128, 2);
    sgemm128<<<gNode, 256>>>(node_features, proj_W, proj_b, px, NN, IND, HID, HID);
    convert_x_kernel<<<(PAD_ROWS * 256) / 256, 256>>>();

    for (int l = 0; l < NL; l++) {
        clear_stats_kernel<<<1, 512>>>();
        mmagemm_kernel<<<dim3(RT_TILES, 4), 256, GEMM_SMEM_BYTES>>>(
            l, bq + l * HID, bk + l * HID, bv + l * HID, bskip + l * HID);
        attn_kernel<<<(NN + 7) / 8, 256>>>(edge_attr,
                                           We + (size_t)l * ED * HID,
                                           be + l * HID,
                                           Wbeta + (size_t)l * 3 * HID);
        bnstats_kernel<<<(NN + 127) / 128, 256>>>();
        bnapply_convert_kernel<<<(NN * HID + 255) / 256, 256>>>(
            bng + l * HID, bnb + l * HID, (l < NL - 1) ? 1 : 0);
    }

    clear_pool_kernel<<<(NG * HID + 255) / 256, 256>>>();
    pool_kernel<<<(NN + 127) / 128, 256>>>(batch);
    head_kernel<<<NG, 256>>>(headW, headb, out);
}